// round 12
// baseline (speedup 1.0000x reference)
#include <cuda_runtime.h>
#include <cuda_bf16.h>
#include <math_constants.h>

// Problem constants (fixed shapes)
#define B_   8
#define C_   21
#define H_   512
#define W_   512
#define HW_  (H_ * W_)           // 262144 = 2^18
#define HW_SHIFT 18
#define NPIX (B_ * HW_)          // 2097152
#define MAX_M 0.5f
#define S_    30.0f

#define GRID   1184              // 148 SMs * 8 CTAs -> exact wave-1 capacity
#define TPB    256
#define CHUNKS (NPIX / TPB)      // 8192 chunks of 256 pixels

// Persistent-kernel state. Zero-initialized at module load; the LAST block of
// every launch resets everything, so each graph replay starts clean.
__device__ float        g_counts[C_];
__device__ double       g_loss;
__device__ unsigned int g_arrive;
__device__ unsigned int g_done;

// ---------------------------------------------------------------------------
// Single fused kernel at exactly-full occupancy:
//   __launch_bounds__(256, 8) -> 32 regs (verified R11) -> 8 CTAs/SM.
//   GRID = 1184 = 148*8: every CTA slot filled, all blocks co-resident in
//   wave 1 -> the software grid barrier is deadlock-free.
//
// Work: 8192 chunks of 256 pixels, chunk-strided across blocks (6-7 each).
// Phases: grid-strided histogram -> arrive -> first chunk streamed with
// label-independent math (hides barrier skew) -> barrier wait -> per-block
// m_list -> deferred epilogue -> remaining chunks with the exact R3
// in-loop-margin body -> reduction -> fused finalize -> state reset.
//
// Deferred-chunk identity (validated R10/R11, rel_err 6.4e-7): raw-max
// stabilizer, A = max(sum_exp - e_l, 0) >= 0, d = x_l - maxv <= 0:
//   nll = log(A + exp(S*(d - m))) - S*d + S*m
// exp args <= 0; target term >= exp(-S*MAX_M) = exp(-15): no over/underflow.
// ---------------------------------------------------------------------------
__global__ __launch_bounds__(TPB, 8) void fused_kernel(
        const float* __restrict__ pred,
        const int*   __restrict__ target,
        float*       __restrict__ out) {
    __shared__ int   sh[8][C_];
    __shared__ float s_mlist[C_];
    __shared__ float warp_sums[8];

    const int tid  = threadIdx.x;
    const int wid  = tid >> 5;
    const int lane = tid & 31;

    for (int i = tid; i < 8 * C_; i += TPB) (&sh[0][0])[i] = 0;
    __syncthreads();

    // ---- Phase A: grid-strided histogram over all labels (int4 loads) ----
    {
        const int4* t4 = reinterpret_cast<const int4*>(target);
        const int   n4 = NPIX / 4;
        for (int i = blockIdx.x * TPB + tid; i < n4; i += GRID * TPB) {
            int4 a = __ldg(t4 + i);
            atomicAdd(&sh[wid][a.x], 1);
            atomicAdd(&sh[wid][a.y], 1);
            atomicAdd(&sh[wid][a.z], 1);
            atomicAdd(&sh[wid][a.w], 1);
        }
    }
    __syncthreads();

    if (tid < C_) {
        int s = 0;
#pragma unroll
        for (int w = 0; w < 8; w++) s += sh[w][tid];
        atomicAdd(&g_counts[tid], (float)s);   // exact: totals < 2^24
    }
    if (tid == 0) {
        __threadfence();                        // counts visible before arrive
        atomicAdd(&g_arrive, 1u);
    }

    // ---- Deferred streaming: first chunk, label-independent parts ----
    float A, D;
    {
        int n  = blockIdx.x * TPB + tid;        // chunk c = blockIdx.x
        int b  = n >> HW_SHIFT;
        int hw = n & (HW_ - 1);
        const float* base = pred + (size_t)(b * C_) * HW_ + hw;
        int l = __ldg(target + n);              // L2 hit (just streamed)

        float v[C_];
        float maxv = -CUDART_INF_F, xl = 0.0f;
#pragma unroll
        for (int c = 0; c < C_; c++) {
            float x = __ldg(base + (size_t)c * HW_);
            v[c] = x;
            maxv = fmaxf(maxv, x);
            if (c == l) xl = x;
        }
        float s = 0.0f;
#pragma unroll
        for (int c = 0; c < C_; c++)
            s += __expf(S_ * (v[c] - maxv));

        float el = __expf(S_ * (xl - maxv));
        A = fmaxf(s - el, 0.0f);
        D = xl - maxv;
    }

    // ---- Grid barrier (hidden behind the deferred chunk) + m_list ----
    if (tid == 0) {
        while (atomicAdd(&g_arrive, 0u) < GRID) __nanosleep(100);
    }
    __syncthreads();
    __threadfence();   // acquire counts written by other blocks

    if (wid == 0) {
        float mi = 0.0f, m = -CUDART_INF_F;
        if (lane < C_) {
            float c = atomicAdd(&g_counts[lane], 0.0f);  // coherent read
            mi = rsqrtf(sqrtf(c + 1e-4f));
            m  = mi;
        }
#pragma unroll
        for (int o = 16; o > 0; o >>= 1)
            m = fmaxf(m, __shfl_xor_sync(0xffffffffu, m, o));
        if (lane < C_) s_mlist[lane] = mi * (MAX_M / m);
    }
    __syncthreads();

    // ---- Epilogue for the deferred chunk ----
    float acc;
    {
        int   l = __ldg(target + blockIdx.x * TPB + tid);
        float m = s_mlist[l];
        acc = __logf(A + __expf(S_ * (D - m))) - S_ * D + S_ * m;
    }

    // ---- Remaining chunks: exact R3 in-loop-margin body ----
#pragma unroll 1
    for (int c0 = blockIdx.x + GRID; c0 < CHUNKS; c0 += GRID) {
        int n  = c0 * TPB + tid;
        int b  = n >> HW_SHIFT;
        int hw = n & (HW_ - 1);
        const float* base = pred + (size_t)(b * C_) * HW_ + hw;
        int   l = __ldg(target + n);
        float m = s_mlist[l];

        float v[C_];
        float maxv = -CUDART_INF_F, vl = 0.0f;
#pragma unroll
        for (int c = 0; c < C_; c++) {
            float x = __ldg(base + (size_t)c * HW_);
            if (c == l) x -= m;
            v[c] = x;
            maxv = fmaxf(maxv, x);
            if (c == l) vl = x;
        }
        float s = 0.0f;
#pragma unroll
        for (int c = 0; c < C_; c++)
            s += __expf(S_ * (v[c] - maxv));

        acc += __logf(s) + S_ * (maxv - vl);
    }

    // ---- Block reduction -> f64 atomic -> fused finalize + state reset ----
#pragma unroll
    for (int o = 16; o > 0; o >>= 1)
        acc += __shfl_xor_sync(0xffffffffu, acc, o);
    if (lane == 0) warp_sums[wid] = acc;
    __syncthreads();

    if (wid == 0) {
        float x = (lane < 8) ? warp_sums[lane] : 0.0f;
#pragma unroll
        for (int o = 4; o > 0; o >>= 1)
            x += __shfl_xor_sync(0xffffffffu, x, o);
        if (lane == 0) {
            atomicAdd(&g_loss, (double)x);
            __threadfence();
            unsigned int done = atomicAdd(&g_done, 1u);
            if (done == GRID - 1) {
                // All blocks fully finished (each passed the barrier first).
                double total = atomicAdd(&g_loss, 0.0);
                out[0] = (float)(total * (1.0 / (double)NPIX));
                // Reset state for the next graph replay.
#pragma unroll
                for (int c = 0; c < C_; c++) g_counts[c] = 0.0f;
                g_loss   = 0.0;
                g_arrive = 0u;
                __threadfence();
                g_done   = 0u;
            }
        }
    }
}

// ---------------------------------------------------------------------------
extern "C" void kernel_launch(void* const* d_in, const int* in_sizes, int n_in,
                              void* d_out, int out_size) {
    const float* pred   = (const float*)d_in[0];
    const int*   target = (const int*)d_in[1];
    float*       out    = (float*)d_out;

    fused_kernel<<<GRID, TPB>>>(pred, target, out);
}